// round 3
// baseline (speedup 1.0000x reference)
#include <cuda_runtime.h>

// Problem constants (fixed by the reference):
//   B=256, T=2048, I=2, H=128, 3H=384
#define BB 256
#define TT 2048
#define HH 128
#define NTHREADS 384
#define NSM 148

__device__ int d_order[BB];

// Placement-aware scheduling. Classic launches map bid -> LUT[bid % 148], so
// bid k and bid k+148 share an SM and (at occupancy 1) run SEQUENTIALLY.
// Assign: slots 108..147 <- 40 longest sequences (alone, <= 2048 steps);
//         slot k (0..107) <- rank 40+k, slot 148+k <- rank 255-k
//         (complementary pairs, each SM totals ~1740 steps).
// Makespan ~= max(2048, ~1740) = 2048 = the serial floor.
__global__ void order_kernel(const int* __restrict__ lengths) {
    int i = threadIdx.x;
    int li = lengths[i];
    int rank = 0;
    #pragma unroll 8
    for (int j = 0; j < BB; j++) {
        int lj = lengths[j];
        rank += (lj > li) || (lj == li && j < i);   // descending, unique
    }
    int slot;
    if (rank < 40)            slot = 108 + rank;          // longest 40: alone
    else if (rank < NSM)      slot = rank - 40;           // pair anchor
    else                      slot = NSM + (BB - 1 - rank); // complement
    d_order[slot] = i;
}

// ---- packed f32x2 helpers (FFMA2 path; ptxas won't auto-fuse from C++) ----
__device__ __forceinline__ unsigned long long fma2(unsigned long long a,
                                                   unsigned long long b,
                                                   unsigned long long c) {
    unsigned long long d;
    asm("fma.rn.f32x2 %0, %1, %2, %3;" : "=l"(d) : "l"(a), "l"(b), "l"(c));
    return d;
}
__device__ __forceinline__ unsigned long long pack2(float x, float y) {
    unsigned long long r;
    asm("mov.b64 %0, {%1, %2};" : "=l"(r) : "f"(x), "f"(y));
    return r;
}
__device__ __forceinline__ void unpack2(unsigned long long v, float& x, float& y) {
    asm("mov.b64 {%0, %1}, %2;" : "=f"(x), "=f"(y) : "l"(v));
}

// MUFU.TANH (single-op, ~16 cyc latency).
__device__ __forceinline__ float tanh_fast(float v) {
    float r;
    asm("tanh.approx.f32 %0, %1;" : "=f"(r) : "f"(v));
    return r;
}
// Sigmoid via MUFU.TANH: sigma(v) = 0.5 + 0.5*tanh(v/2). Abs err ~2.5e-4;
// used only for r/z gates whose error enters h damped.
__device__ __forceinline__ float fsigmoid(float v) {
    return fmaf(0.5f, tanh_fast(0.5f * v), 0.5f);
}
// Accurate tanh for the n gate (error enters h undamped): EX2+RCP, ~1e-6.
__device__ __forceinline__ float ftanh_acc(float v) {
    float e = __expf(2.0f * v);
    return 1.0f - __fdividef(2.0f, e + 1.0f);
}

__global__ void __launch_bounds__(NTHREADS, 1)
gru_kernel(const float* __restrict__ x,        // [B, T, 2]
           const int*   __restrict__ lengths,  // [B]
           const float* __restrict__ W_ih,     // [384, 2]
           const float* __restrict__ W_hh,     // [384, 128]
           const float* __restrict__ b_ih,     // [384]
           const float* __restrict__ b_hh,     // [384]
           const float* __restrict__ head_w,   // [128]
           const float* __restrict__ head_b,   // [1]
           float*       __restrict__ out)      // [B, 1]
{
    __shared__ __align__(16) float sh_x[TT * 2];   // full input sequence: 16 KB
    __shared__ __align__(16) float sh_h[HH];       // hidden state
    __shared__ float sh_g[2 * HH];                 // z/n partial gates

    const int tid = threadIdx.x;
    const int b = d_order[blockIdx.x];
    const int len = lengths[b];

    // --- load this sequence's inputs into shared (only the needed prefix) ---
    {
        const float4* xs = reinterpret_cast<const float4*>(x + (size_t)b * (TT * 2));
        float4* xd = reinterpret_cast<float4*>(sh_x);
        int nq = (len * 2 + 3) >> 2;
        for (int q = tid; q < nq; q += NTHREADS) xd[q] = xs[q];
    }

    // --- load W_hh row `tid` into 64 packed f32x2 registers ---
    unsigned long long w[64];
    {
        const unsigned long long* wrow =
            reinterpret_cast<const unsigned long long*>(W_hh + (size_t)tid * HH);
        #pragma unroll
        for (int t = 0; t < 64; t++) w[t] = wrow[t];
    }
    const float bhh = b_hh[tid];

    // --- per-thread gate constants for the combiner threads (tid < 128) ---
    float wr0 = 0.f, wr1 = 0.f, wz0 = 0.f, wz1 = 0.f, wn0 = 0.f, wn1 = 0.f;
    float br = 0.f, bz = 0.f, bn = 0.f;
    float h = 0.0f;
    float hw = 0.0f;
    if (tid < HH) {
        float2 t2;
        t2 = *reinterpret_cast<const float2*>(W_ih + (size_t)tid * 2);
        wr0 = t2.x; wr1 = t2.y;
        t2 = *reinterpret_cast<const float2*>(W_ih + (size_t)(HH + tid) * 2);
        wz0 = t2.x; wz1 = t2.y;
        t2 = *reinterpret_cast<const float2*>(W_ih + (size_t)(2 * HH + tid) * 2);
        wn0 = t2.x; wn1 = t2.y;
        br = b_ih[tid];
        bz = b_ih[HH + tid];
        bn = b_ih[2 * HH + tid];
        sh_h[tid] = 0.0f;
        hw = head_w[tid];
    }
    __syncthreads();

    // --- recurrence ---
    for (int t = 0; t < len; t++) {
        // Hoist the (h-independent) x(t) read so its LDS latency overlaps
        // the matvec instead of sitting on the gate-phase critical path.
        float x0 = 0.f, x1 = 0.f;
        if (tid < HH) {
            float2 xt = *reinterpret_cast<const float2*>(sh_x + 2 * t);
            x0 = xt.x; x1 = xt.y;
        }

        // gh[tid] = b_hh[tid] + sum_k W_hh[tid][k] * h[k]
        // 4 independent FMA2 chains give ptxas slack to hoist LDS.128s.
        unsigned long long acc0 = pack2(bhh, 0.0f);
        unsigned long long acc1 = pack2(0.0f, 0.0f);
        unsigned long long acc2 = acc1, acc3 = acc1;
        const ulonglong2* h2 = reinterpret_cast<const ulonglong2*>(sh_h);
        #pragma unroll
        for (int k = 0; k < 16; k++) {
            ulonglong2 ha = h2[2 * k];
            ulonglong2 hb = h2[2 * k + 1];
            acc0 = fma2(w[4 * k + 0], ha.x, acc0);
            acc1 = fma2(w[4 * k + 1], ha.y, acc1);
            acc2 = fma2(w[4 * k + 2], hb.x, acc2);
            acc3 = fma2(w[4 * k + 3], hb.y, acc3);
        }
        float a0x, a0y, a1x, a1y, a2x, a2y, a3x, a3y;
        unpack2(acc0, a0x, a0y);
        unpack2(acc1, a1x, a1y);
        unpack2(acc2, a2x, a2y);
        unpack2(acc3, a3x, a3y);
        float gh = ((a0x + a0y) + (a1x + a1y)) + ((a2x + a2y) + (a3x + a3y));

        if (tid >= HH) sh_g[tid - HH] = gh;   // z and n partials to shared
        __syncthreads();

        if (tid < HH) {
            float hr = gh;                    // own row is the r-gate
            float hz = sh_g[tid];
            float hn = sh_g[HH + tid];
            float r = fsigmoid(fmaf(wr0, x0, fmaf(wr1, x1, br)) + hr);
            float z = fsigmoid(fmaf(wz0, x0, fmaf(wz1, x1, bz)) + hz);
            float n = ftanh_acc(fmaf(wn0, x0, fmaf(wn1, x1, bn)) + r * hn);
            h = fmaf(z, h - n, n);            // (1-z)*n + z*h
            sh_h[tid] = h;
        }
        __syncthreads();
    }

    // --- head: out[b] = sum_j h[j]*head_w[j] + head_b ---
    float v = (tid < HH) ? h * hw : 0.0f;
    #pragma unroll
    for (int o = 16; o > 0; o >>= 1) v += __shfl_down_sync(0xffffffffu, v, o);
    if ((tid & 31) == 0) sh_g[tid >> 5] = v;
    __syncthreads();
    if (tid == 0) {
        float s = 0.0f;
        #pragma unroll
        for (int wi = 0; wi < NTHREADS / 32; wi++) s += sh_g[wi];
        out[b] = s + head_b[0];
    }
}

extern "C" void kernel_launch(void* const* d_in, const int* in_sizes, int n_in,
                              void* d_out, int out_size) {
    const float* x      = (const float*)d_in[0];
    const int*   len    = (const int*)  d_in[1];
    const float* W_ih   = (const float*)d_in[2];
    const float* W_hh   = (const float*)d_in[3];
    const float* b_ih   = (const float*)d_in[4];
    const float* b_hh   = (const float*)d_in[5];
    const float* head_w = (const float*)d_in[6];
    const float* head_b = (const float*)d_in[7];
    float* out = (float*)d_out;

    order_kernel<<<1, BB>>>(len);
    gru_kernel<<<BB, NTHREADS>>>(x, len, W_ih, W_hh, b_ih, b_hh,
                                 head_w, head_b, out);
}

// round 4
// speedup vs baseline: 1.1739x; 1.1739x over previous
#include <cuda_runtime.h>

// Problem constants: B=256, T=2048, I=2, H=128, 3H=384
#define BB 256
#define TT 2048
#define HH 128
#define NTHREADS 384

__device__ int d_order[BB];

// Plain descending-length order. Wave 1 = 148 longest; wave-2 CTAs are
// work-stolen in bid order = longest-remaining-first = LPT.
__global__ void order_kernel(const int* __restrict__ lengths) {
    int i = threadIdx.x;
    int li = lengths[i];
    int rank = 0;
    #pragma unroll 8
    for (int j = 0; j < BB; j++) {
        int lj = lengths[j];
        rank += (lj > li) || (lj == li && j < i);
    }
    d_order[rank] = i;
}

// ---- packed f32x2 helpers ----
__device__ __forceinline__ unsigned long long fma2(unsigned long long a,
                                                   unsigned long long b,
                                                   unsigned long long c) {
    unsigned long long d;
    asm("fma.rn.f32x2 %0, %1, %2, %3;" : "=l"(d) : "l"(a), "l"(b), "l"(c));
    return d;
}
__device__ __forceinline__ unsigned long long add2(unsigned long long a,
                                                   unsigned long long b) {
    unsigned long long d;
    asm("add.rn.f32x2 %0, %1, %2;" : "=l"(d) : "l"(a), "l"(b));
    return d;
}
__device__ __forceinline__ unsigned long long pack2(float x, float y) {
    unsigned long long r;
    asm("mov.b64 %0, {%1, %2};" : "=l"(r) : "f"(x), "f"(y));
    return r;
}
__device__ __forceinline__ void unpack2(unsigned long long v, float& x, float& y) {
    asm("mov.b64 {%0, %1}, %2;" : "=f"(x), "=f"(y) : "l"(v));
}

// Single-MUFU tanh (~16 cyc). R3 measured: approx gates cost only ~3e-7 rel_err.
__device__ __forceinline__ float tanh_fast(float v) {
    float r;
    asm("tanh.approx.f32 %0, %1;" : "=f"(r) : "f"(v));
    return r;
}
__device__ __forceinline__ float fsigmoid(float v) {
    return fmaf(0.5f, tanh_fast(0.5f * v), 0.5f);
}

// Thread roles: tid 0..127 -> z-rows (128+j); tid 128..255 -> n-rows (256+j);
// tid 256..383 -> r-rows (j) + combiner (highest warps = issue priority).
// Trio t = {warp t, warp t+4, warp t+8} syncs via named barrier 1+t (96 thr).
__global__ void __launch_bounds__(NTHREADS, 1)
gru_kernel(const float* __restrict__ x,        // [B, T, 2]
           const int*   __restrict__ lengths,  // [B]
           const float* __restrict__ W_ih,     // [384, 2]
           const float* __restrict__ W_hh,     // [384, 128]
           const float* __restrict__ b_ih,     // [384]
           const float* __restrict__ b_hh,     // [384]
           const float* __restrict__ head_w,   // [128]
           const float* __restrict__ head_b,   // [1]
           float*       __restrict__ out)      // [B, 1]
{
    __shared__ __align__(16) float sh_x[TT * 2];     // 16 KB
    __shared__ __align__(16) float sh_h[2][HH];      // ping-pong hidden state
    __shared__ float sh_gz[HH];
    __shared__ float sh_gn[HH];
    __shared__ float sh_red[4];

    const int tid = threadIdx.x;
    const int b = d_order[blockIdx.x];
    const int len = lengths[b];

    const int role = tid >> 7;            // 0=z, 1=n, 2=r/combiner
    const int j = tid & 127;
    const int row = (role == 0) ? (HH + j) : (role == 1) ? (2 * HH + j) : j;
    const int bar_id = 1 + ((tid >> 5) & 3);

    // --- load input prefix into shared ---
    {
        const float4* xs = reinterpret_cast<const float4*>(x + (size_t)b * (TT * 2));
        float4* xd = reinterpret_cast<float4*>(sh_x);
        int nq = (len * 2 + 3) >> 2;
        for (int q = tid; q < nq; q += NTHREADS) xd[q] = xs[q];
    }

    // --- W_hh row into 64 packed f32x2 registers ---
    unsigned long long w[64];
    {
        const unsigned long long* wrow =
            reinterpret_cast<const unsigned long long*>(W_hh + (size_t)row * HH);
        #pragma unroll
        for (int t = 0; t < 64; t++) w[t] = wrow[t];
    }
    const float bhh = b_hh[row];

    // Gate constants (combiners only; zeros elsewhere so the x-projection
    // FMAs run branch-free on all threads).
    float wr0 = 0.f, wr1 = 0.f, wz0 = 0.f, wz1 = 0.f, wn0 = 0.f, wn1 = 0.f;
    float br = 0.f, bz = 0.f, bn = 0.f, hw = 0.f;
    float h = 0.0f;
    if (role == 2) {
        float2 t2;
        t2 = *reinterpret_cast<const float2*>(W_ih + (size_t)j * 2);
        wr0 = t2.x; wr1 = t2.y;
        t2 = *reinterpret_cast<const float2*>(W_ih + (size_t)(HH + j) * 2);
        wz0 = t2.x; wz1 = t2.y;
        t2 = *reinterpret_cast<const float2*>(W_ih + (size_t)(2 * HH + j) * 2);
        wn0 = t2.x; wn1 = t2.y;
        br = b_ih[j];
        bz = b_ih[HH + j];
        bn = b_ih[2 * HH + j];
        hw = head_w[j];
        sh_h[0][j] = 0.0f;
    }
    float* part_dst = ((role == 0) ? sh_gz : sh_gn) + j;   // unused by role 2
    __syncthreads();

    int cur = 0;
    for (int t = 0; t < len; t++) {
        // h-independent x projections (hoisted off the serial tail)
        float2 xt = *reinterpret_cast<const float2*>(sh_x + 2 * t);
        float xr = fmaf(wr0, xt.x, fmaf(wr1, xt.y, br));
        float xz = fmaf(wz0, xt.x, fmaf(wz1, xt.y, bz));
        float xn = fmaf(wn0, xt.x, fmaf(wn1, xt.y, bn));

        // gh = b_hh[row] + W_hh[row] . h   (4 FMA2 chains)
        unsigned long long acc0 = pack2(bhh, 0.0f);
        unsigned long long acc1 = pack2(0.0f, 0.0f);
        unsigned long long acc2 = acc1, acc3 = acc1;
        const ulonglong2* h2 = reinterpret_cast<const ulonglong2*>(sh_h[cur]);
        #pragma unroll
        for (int k = 0; k < 16; k++) {
            ulonglong2 ha = h2[2 * k];
            ulonglong2 hb = h2[2 * k + 1];
            acc0 = fma2(w[4 * k + 0], ha.x, acc0);
            acc1 = fma2(w[4 * k + 1], ha.y, acc1);
            acc2 = fma2(w[4 * k + 2], hb.x, acc2);
            acc3 = fma2(w[4 * k + 3], hb.y, acc3);
        }
        unsigned long long s = add2(add2(acc0, acc1), add2(acc2, acc3));
        float slo, shi;
        unpack2(s, slo, shi);
        float gh = slo + shi;

        if (role != 2) {
            *part_dst = gh;                               // z or n partial
            asm volatile("bar.arrive %0, 96;" :: "r"(bar_id) : "memory");
        } else {
            asm volatile("bar.sync %0, 96;" :: "r"(bar_id) : "memory");
            float gzv = sh_gz[j];
            float gnv = sh_gn[j];
            float r = fsigmoid(xr + gh);                  // own row is r
            float z = fsigmoid(xz + gzv);
            float n = tanh_fast(fmaf(r, gnv, xn));
            h = fmaf(z, h - n, n);                        // (1-z)*n + z*h
            sh_h[cur ^ 1][j] = h;
        }
        __syncthreads();
        cur ^= 1;
    }

    // --- head: out[b] = sum_j h[j]*head_w[j] + head_b (combiners hold h) ---
    if (role == 2) {
        float v = h * hw;
        #pragma unroll
        for (int o = 16; o > 0; o >>= 1) v += __shfl_down_sync(0xffffffffu, v, o);
        if ((tid & 31) == 0) sh_red[(tid >> 5) - 8] = v;
    }
    __syncthreads();
    if (tid == 256) {
        out[b] = (sh_red[0] + sh_red[1]) + (sh_red[2] + sh_red[3]) + head_b[0];
    }
}

extern "C" void kernel_launch(void* const* d_in, const int* in_sizes, int n_in,
                              void* d_out, int out_size) {
    const float* x      = (const float*)d_in[0];
    const int*   len    = (const int*)  d_in[1];
    const float* W_ih   = (const float*)d_in[2];
    const float* W_hh   = (const float*)d_in[3];
    const float* b_ih   = (const float*)d_in[4];
    const float* b_hh   = (const float*)d_in[5];
    const float* head_w = (const float*)d_in[6];
    const float* head_b = (const float*)d_in[7];
    float* out = (float*)d_out;

    order_kernel<<<1, BB>>>(len);
    gru_kernel<<<BB, NTHREADS>>>(x, len, W_ih, W_hh, b_ih, b_hh,
                                 head_w, head_b, out);
}